// round 9
// baseline (speedup 1.0000x reference)
#include <cuda_runtime.h>
#include <math.h>
#include <stdint.h>

#define TOKENS     8192
#define MODEL_DIM  4096
#define PROMPT_DIM 64
#define KTOT       (MODEL_DIM + PROMPT_DIM)   // 4160
#define NE         8
#define NP         4                          // expert pairs
#define TPW        8                          // tokens per warp
#define WARPS      8
#define THREADS    256
#define TPB        64                         // tokens per CTA
#define DSTRIDE    4162                       // per-pair W row, float2 units
#define W_BYTES    (NP * DSTRIDE * 8)         // 133,184 B
#define CHUNK      64                         // dims per stage chunk (256 B per token)
#define NIT        (MODEL_DIM / CHUNK)        // 64
#define NSTAGE     5
#define STAGE_FLOATS (TPB * CHUNK)            // 4096 floats = 16 KB
#define STAGE_BYTES  (STAGE_FLOATS * 4)
#define MBAR_AREA  128                        // full[5] @0, empty[5] @64
#define SMEM_BYTES (MBAR_AREA + W_BYTES + NSTAGE * STAGE_BYTES)   // 215,232 B

// ---- mbarrier / bulk-copy helpers ----
__device__ __forceinline__ void mbar_init(uint32_t a, uint32_t cnt) {
    asm volatile("mbarrier.init.shared.b64 [%0], %1;" :: "r"(a), "r"(cnt) : "memory");
}
__device__ __forceinline__ void mbar_arrive(uint32_t a) {
    asm volatile("mbarrier.arrive.shared.b64 _, [%0];" :: "r"(a) : "memory");
}
__device__ __forceinline__ void mbar_expect_tx(uint32_t a, uint32_t bytes) {
    asm volatile("mbarrier.arrive.expect_tx.shared.b64 _, [%0], %1;"
                 :: "r"(a), "r"(bytes) : "memory");
}
__device__ __forceinline__ void mbar_wait(uint32_t mbar, uint32_t phase) {
    asm volatile(
        "{\n\t"
        ".reg .pred P;\n\t"
        "WAIT_%=:\n\t"
        "mbarrier.try_wait.parity.acquire.cta.shared::cta.b64 P, [%0], %1, 0x989680;\n\t"
        "@P bra.uni DONE_%=;\n\t"
        "bra.uni WAIT_%=;\n\t"
        "DONE_%=:\n\t"
        "}"
        :: "r"(mbar), "r"(phase) : "memory");
}
// Engine-driven bulk copy global -> SMEM, completion via mbarrier tx bytes
__device__ __forceinline__ void bulk_g2s(uint32_t sdst, const void* gsrc,
                                         uint32_t bytes, uint32_t mbar) {
    asm volatile(
        "cp.async.bulk.shared::cluster.global.mbarrier::complete_tx::bytes "
        "[%0], [%1], %2, [%3];"
        :: "r"(sdst), "l"(gsrc), "r"(bytes), "r"(mbar) : "memory");
}
// ---- packed fp32x2 ops ----
__device__ __forceinline__ void ffma2(unsigned long long& d,
                                      unsigned long long a,
                                      unsigned long long b) {
    asm("fma.rn.f32x2 %0, %1, %2, %0;" : "+l"(d) : "l"(a), "l"(b));
}
__device__ __forceinline__ unsigned long long dup2(float v) {
    unsigned long long r;
    asm("mov.b64 %0, {%1, %1};" : "=l"(r) : "f"(v));
    return r;
}
__device__ __forceinline__ void unpack2(unsigned long long v, float& lo, float& hi) {
    asm("mov.b64 {%0, %1}, %2;" : "=f"(lo), "=f"(hi) : "l"(v));
}

__global__ __launch_bounds__(THREADS, 1)
void topkgate_kernel(const float* __restrict__ x,
                     const float* __restrict__ prompt,
                     const float* __restrict__ W,
                     const float* __restrict__ b,
                     float* __restrict__ out)
{
    extern __shared__ __align__(16) char smem_raw[];
    const uint32_t smem_u32 = (uint32_t)__cvta_generic_to_shared(smem_raw);
    float2* wsp = (float2*)(smem_raw + MBAR_AREA);                  // paired W
    float*  stg = (float*)(smem_raw + MBAR_AREA + W_BYTES);         // 5 stages
    const uint32_t stg_u32 = smem_u32 + MBAR_AREA + W_BYTES;

    const int tid   = threadIdx.x;
    const int w     = tid >> 5;
    const int lane  = tid & 31;
    const int tbase = blockIdx.x * TPB;

    // ---- Init mbarriers: full (tx-based, count 1), empty (count = THREADS) ----
    if (tid == 0) {
#pragma unroll
        for (int s = 0; s < NSTAGE; s++) {
            mbar_init(smem_u32 + s * 8, 1);               // full[s]
            mbar_init(smem_u32 + 64 + s * 8, THREADS);    // empty[s]
        }
    }

    // ---- Stage W into expert-paired SMEM layout ----
    {
        const float2* Wv = (const float2*)W;   // Wv[d*4 + p] = (W[d][2p], W[d][2p+1])
        for (int i = tid; i < KTOT * NP; i += THREADS) {
            int d = i >> 2;
            int p = i & 3;
            wsp[p * DSTRIDE + d] = Wv[i];
        }
    }
    __syncthreads();   // mbarriers + W visible

    // ---- Producer setup: thread tid (< 64) feeds token tid's 256 B per stage ----
    const char* gsrc = (const char*)(x + (size_t)(tbase + (tid & 63)) * MODEL_DIM);
    const uint32_t sdst0 = stg_u32 + (uint32_t)((tid & 63) * 256);

    // Prologue: fill stages 0..3 (barriers fresh — no empty-wait needed)
    if (tid < 64) {
#pragma unroll
        for (int j = 0; j < NSTAGE - 1; j++) {
            if (tid == 0) mbar_expect_tx(smem_u32 + j * 8, STAGE_BYTES);
            bulk_g2s(sdst0 + j * STAGE_BYTES, gsrc + (size_t)j * 256,
                     256, smem_u32 + j * 8);
        }
    }

    // Packed accumulators: acc[m][p] = (logit[2p], logit[2p+1]) partial sums
    unsigned long long acc[TPW][NP];
#pragma unroll
    for (int m = 0; m < TPW; m++)
#pragma unroll
        for (int p = 0; p < NP; p++) acc[m][p] = 0ull;

    const uint32_t xlane = (uint32_t)((w * TPW) * CHUNK + 2 * lane);

    // ---- Mainloop: mbarrier-pipelined, no CTA barriers ----
    for (int it = 0; it < NIT; ++it) {
        // Produce chunk it+4 into slot (it+4)%5
        const int jn = it + NSTAGE - 1;
        if (tid < 64 && jn < NIT) {
            const int ps = jn % NSTAGE;
            mbar_wait(smem_u32 + 64 + ps * 8, ((jn / NSTAGE) & 1) ^ 1);   // empty
            if (tid == 0) mbar_expect_tx(smem_u32 + ps * 8, STAGE_BYTES);
            bulk_g2s(sdst0 + ps * STAGE_BYTES, gsrc + (size_t)jn * 256,
                     256, smem_u32 + ps * 8);
        }

        // Consume chunk it from slot it%5
        const int slot = it % NSTAGE;
        mbar_wait(smem_u32 + slot * 8, (it / NSTAGE) & 1);                // full

        const float* xw = stg + slot * STAGE_FLOATS + xlane;
        const int d0 = it * CHUNK + 2 * lane;

        ulonglong2 wv[NP];
#pragma unroll
        for (int p = 0; p < NP; p++)
            wv[p] = *(const ulonglong2*)&wsp[p * DSTRIDE + d0];
        // wv[p].x = (W[d0][2p], W[d0][2p+1]); wv[p].y = same for dim d0+1

#pragma unroll
        for (int m = 0; m < TPW; m++) {
            const float2 xv = *(const float2*)(xw + m * CHUNK);
            const unsigned long long xlo = dup2(xv.x);
            const unsigned long long xhi = dup2(xv.y);
#pragma unroll
            for (int p = 0; p < NP; p++) {
                ffma2(acc[m][p], xlo, wv[p].x);
                ffma2(acc[m][p], xhi, wv[p].y);
            }
        }

        mbar_arrive(smem_u32 + 64 + slot * 8);                            // empty
    }

    // ---- Prompt tail: lane handles dims (4096 + 2*lane, +1) for its tokens ----
    {
        const int po = MODEL_DIM + 2 * lane;
        ulonglong2 wp[NP];
#pragma unroll
        for (int p = 0; p < NP; p++)
            wp[p] = *(const ulonglong2*)&wsp[p * DSTRIDE + po];
#pragma unroll
        for (int m = 0; m < TPW; m++) {
            const int t = tbase + w * TPW + m;
            const float2 pv = *(const float2*)(prompt + (size_t)t * PROMPT_DIM + 2 * lane);
            const unsigned long long plo = dup2(pv.x);
            const unsigned long long phi = dup2(pv.y);
#pragma unroll
            for (int p = 0; p < NP; p++) {
                ffma2(acc[m][p], plo, wp[p].x);
                ffma2(acc[m][p], phi, wp[p].y);
            }
        }
    }

    // ---- Unpack to scalar accumulators ----
    float accf[TPW][NE];
#pragma unroll
    for (int m = 0; m < TPW; m++)
#pragma unroll
        for (int p = 0; p < NP; p++)
            unpack2(acc[m][p], accf[m][2 * p], accf[m][2 * p + 1]);

    // ---- Warp butterfly reduction over lanes ----
#pragma unroll
    for (int off = 16; off > 0; off >>= 1) {
#pragma unroll
        for (int m = 0; m < TPW; m++)
#pragma unroll
            for (int e = 0; e < NE; e++)
                accf[m][e] += __shfl_xor_sync(0xffffffffu, accf[m][e], off);
    }

    // ---- Epilogue: lane m handles token (w*TPW + m) ----
    if (lane < TPW) {
        const int t = tbase + w * TPW + lane;

        float lg[NE];
#pragma unroll
        for (int m = 0; m < TPW; m++) {
            if (lane == m) {
#pragma unroll
                for (int e = 0; e < NE; e++) lg[e] = accf[m][e];
            }
        }
#pragma unroll
        for (int e = 0; e < NE; e++) lg[e] += b[e];

        // Top-2 with first-index tie-break (matches jax.lax.top_k)
        int i0 = 0; float m0 = lg[0];
#pragma unroll
        for (int e = 1; e < NE; e++)
            if (lg[e] > m0) { m0 = lg[e]; i0 = e; }
        int i1 = -1; float m1 = -INFINITY;
#pragma unroll
        for (int e = 0; e < NE; e++)
            if (e != i0 && lg[e] > m1) { m1 = lg[e]; i1 = e; }

        // Softmax over 8 (max-subtracted), gather top-2, renormalize with EPS clamp
        float s = 0.0f;
#pragma unroll
        for (int e = 0; e < NE; e++) s += __expf(lg[e] - m0);
        const float g0 = 1.0f / s;
        const float g1 = __expf(m1 - m0) / s;
        const float denom = fmaxf(g0 + g1, 1.1920929e-07f);
        const float r0 = g0 / denom;
        const float r1 = g1 / denom;

        // masks: [T, 2, 8] at offset 0
        float* mrow = out + (size_t)t * 16;
        const float4 z = make_float4(0.f, 0.f, 0.f, 0.f);
        *(float4*)(mrow + 0)  = z;
        *(float4*)(mrow + 4)  = z;
        *(float4*)(mrow + 8)  = z;
        *(float4*)(mrow + 12) = z;
        mrow[i0]     = 1.0f;
        mrow[8 + i1] = 1.0f;

        // gates_s: [T, 2] at offset T*16
        float* grow = out + (size_t)TOKENS * 16 + (size_t)t * 2;
        grow[0] = r0;
        grow[1] = r1;
    }
}

extern "C" void kernel_launch(void* const* d_in, const int* in_sizes, int n_in,
                              void* d_out, int out_size)
{
    const float* x      = (const float*)d_in[0];
    const float* prompt = (const float*)d_in[1];
    const float* W      = (const float*)d_in[2];
    const float* b      = (const float*)d_in[3];
    float* out          = (float*)d_out;

    cudaFuncSetAttribute(topkgate_kernel,
                         cudaFuncAttributeMaxDynamicSharedMemorySize, SMEM_BYTES);

    dim3 grid(TOKENS / TPB);   // 128 blocks, one wave
    topkgate_kernel<<<grid, THREADS, SMEM_BYTES>>>(x, prompt, W, b, out);
}

// round 10
// speedup vs baseline: 2.1495x; 2.1495x over previous
#include <cuda_runtime.h>
#include <cuda.h>
#include <math.h>
#include <stdint.h>
#include <string.h>

#define TOKENS     8192
#define MODEL_DIM  4096
#define PROMPT_DIM 64
#define KTOT       (MODEL_DIM + PROMPT_DIM)   // 4160
#define NE         8
#define NP         4                          // expert pairs
#define DSTRIDE    4162                       // per-pair W row, float2 units
#define W_BYTES    (NP * DSTRIDE * 8)         // 133,184 B
#define CHUNK      64                         // dims per stage chunk
#define NIT        (MODEL_DIM / CHUNK)        // 64

// ---- TMA kernel config ----
#define T_TPW      8
#define T_WARPS    8
#define T_THREADS  256
#define TPB        64                         // tokens per CTA
#define NSTAGE     5
#define STAGE_BYTES 16384                     // 64 tokens x 256 B
#define MBAR_AREA  192                        // full[5]@0, empty[5]@64; stages 128B-aligned
#define T_SMEM     (MBAR_AREA + W_BYTES + NSTAGE * STAGE_BYTES)   // 215,296 B

// ---- Fallback (R6) config ----
#define F_TPW      2
#define F_THREADS  1024
#define F_SMEM     (NP * DSTRIDE * 8)         // 133,184 B
#define RING       4

// ================= PTX helpers =================
__device__ __forceinline__ void mbar_init(uint32_t a, uint32_t cnt) {
    asm volatile("mbarrier.init.shared.b64 [%0], %1;" :: "r"(a), "r"(cnt) : "memory");
}
__device__ __forceinline__ void mbar_arrive(uint32_t a) {
    asm volatile("mbarrier.arrive.shared.b64 _, [%0];" :: "r"(a) : "memory");
}
__device__ __forceinline__ void mbar_expect_tx(uint32_t a, uint32_t bytes) {
    asm volatile("mbarrier.arrive.expect_tx.shared.b64 _, [%0], %1;"
                 :: "r"(a), "r"(bytes) : "memory");
}
__device__ __forceinline__ void mbar_wait(uint32_t mbar, uint32_t phase) {
    asm volatile(
        "{\n\t"
        ".reg .pred P;\n\t"
        "WAIT_%=:\n\t"
        "mbarrier.try_wait.parity.acquire.cta.shared::cta.b64 P, [%0], %1, 0x989680;\n\t"
        "@P bra.uni DONE_%=;\n\t"
        "bra.uni WAIT_%=;\n\t"
        "DONE_%=:\n\t"
        "}"
        :: "r"(mbar), "r"(phase) : "memory");
}
__device__ __forceinline__ void tma_load_2d(uint32_t sdst, const void* tmap,
                                            int cx, int cy, uint32_t mbar) {
    asm volatile(
        "cp.async.bulk.tensor.2d.shared::cta.global.tile.mbarrier::complete_tx::bytes "
        "[%0], [%1, {%2, %3}], [%4];"
        :: "r"(sdst), "l"(tmap), "r"(cx), "r"(cy), "r"(mbar) : "memory");
}
__device__ __forceinline__ void ffma2(unsigned long long& d,
                                      unsigned long long a,
                                      unsigned long long b) {
    asm("fma.rn.f32x2 %0, %1, %2, %0;" : "+l"(d) : "l"(a), "l"(b));
}
__device__ __forceinline__ unsigned long long dup2(float v) {
    unsigned long long r;
    asm("mov.b64 %0, {%1, %1};" : "=l"(r) : "f"(v));
    return r;
}
__device__ __forceinline__ void unpack2(unsigned long long v, float& lo, float& hi) {
    asm("mov.b64 {%0, %1}, %2;" : "=f"(lo), "=f"(hi) : "l"(v));
}

// ================= Shared epilogue (per token) =================
__device__ __forceinline__ void gate_epilogue(const float* lg_in, const float* __restrict__ b,
                                              int t, float* __restrict__ out) {
    float lg[NE];
#pragma unroll
    for (int e = 0; e < NE; e++) lg[e] = lg_in[e] + b[e];

    // Top-2 with first-index tie-break (matches jax.lax.top_k)
    int i0 = 0; float m0 = lg[0];
#pragma unroll
    for (int e = 1; e < NE; e++)
        if (lg[e] > m0) { m0 = lg[e]; i0 = e; }
    int i1 = -1; float m1 = -INFINITY;
#pragma unroll
    for (int e = 0; e < NE; e++)
        if (e != i0 && lg[e] > m1) { m1 = lg[e]; i1 = e; }

    float s = 0.0f;
#pragma unroll
    for (int e = 0; e < NE; e++) s += __expf(lg[e] - m0);
    const float g0 = 1.0f / s;
    const float g1 = __expf(m1 - m0) / s;
    const float denom = fmaxf(g0 + g1, 1.1920929e-07f);
    const float r0 = g0 / denom;
    const float r1 = g1 / denom;

    float* mrow = out + (size_t)t * 16;
    const float4 z = make_float4(0.f, 0.f, 0.f, 0.f);
    *(float4*)(mrow + 0)  = z;
    *(float4*)(mrow + 4)  = z;
    *(float4*)(mrow + 8)  = z;
    *(float4*)(mrow + 12) = z;
    mrow[i0]     = 1.0f;
    mrow[8 + i1] = 1.0f;

    float* grow = out + (size_t)TOKENS * 16 + (size_t)t * 2;
    grow[0] = r0;
    grow[1] = r1;
}

// ================= TMA kernel =================
__global__ __launch_bounds__(T_THREADS, 1)
void topkgate_tma_kernel(const __grid_constant__ CUtensorMap tmap,
                         const float* __restrict__ prompt,
                         const float* __restrict__ W,
                         const float* __restrict__ b,
                         float* __restrict__ out)
{
    extern __shared__ __align__(128) char smem_raw[];
    const uint32_t smem_u32 = (uint32_t)__cvta_generic_to_shared(smem_raw);
    float2* wsp = (float2*)(smem_raw + MBAR_AREA);
    float*  stg = (float*)(smem_raw + MBAR_AREA + W_BYTES);
    const uint32_t stg_u32 = smem_u32 + MBAR_AREA + W_BYTES;

    const int tid   = threadIdx.x;
    const int w     = tid >> 5;
    const int lane  = tid & 31;
    const int tbase = blockIdx.x * TPB;

    if (tid == 0) {
#pragma unroll
        for (int s = 0; s < NSTAGE; s++) {
            mbar_init(smem_u32 + s * 8, 1);               // full[s] (tx-based)
            mbar_init(smem_u32 + 64 + s * 8, T_THREADS);  // empty[s]
        }
    }

    // Stage W into expert-paired SMEM layout
    {
        const float2* Wv = (const float2*)W;   // Wv[d*4 + p] = (W[d][2p], W[d][2p+1])
        for (int i = tid; i < KTOT * NP; i += T_THREADS) {
            int d = i >> 2;
            int p = i & 3;
            wsp[p * DSTRIDE + d] = Wv[i];
        }
    }
    __syncthreads();   // mbarriers + W visible

    // Prologue: fill stages 0..3 (one 16 KB TMA op each)
    if (tid == 0) {
#pragma unroll
        for (int j = 0; j < NSTAGE - 1; j++) {
            mbar_expect_tx(smem_u32 + j * 8, STAGE_BYTES);
            tma_load_2d(stg_u32 + j * STAGE_BYTES, &tmap, j * CHUNK, tbase,
                        smem_u32 + j * 8);
        }
    }

    unsigned long long acc[T_TPW][NP];
#pragma unroll
    for (int m = 0; m < T_TPW; m++)
#pragma unroll
        for (int p = 0; p < NP; p++) acc[m][p] = 0ull;

    const uint32_t xlane = (uint32_t)((w * T_TPW) * CHUNK + 2 * lane);

    for (int it = 0; it < NIT; ++it) {
        // Produce chunk it+4 into slot (it+4)%5
        const int jn = it + NSTAGE - 1;
        if (tid == 0 && jn < NIT) {
            const int ps = jn % NSTAGE;
            const int g  = jn / NSTAGE;
            if (g >= 1) mbar_wait(smem_u32 + 64 + ps * 8, (g - 1) & 1);   // empty
            mbar_expect_tx(smem_u32 + ps * 8, STAGE_BYTES);
            tma_load_2d(stg_u32 + ps * STAGE_BYTES, &tmap, jn * CHUNK, tbase,
                        smem_u32 + ps * 8);
        }

        // Consume chunk it from slot it%5
        const int slot = it % NSTAGE;
        mbar_wait(smem_u32 + slot * 8, (it / NSTAGE) & 1);                // full

        const float* xw = stg + slot * (STAGE_BYTES / 4) + xlane;
        const int d0 = it * CHUNK + 2 * lane;

        ulonglong2 wv[NP];
#pragma unroll
        for (int p = 0; p < NP; p++)
            wv[p] = *(const ulonglong2*)&wsp[p * DSTRIDE + d0];

#pragma unroll
        for (int m = 0; m < T_TPW; m++) {
            const float2 xv = *(const float2*)(xw + m * CHUNK);
            const unsigned long long xlo = dup2(xv.x);
            const unsigned long long xhi = dup2(xv.y);
#pragma unroll
            for (int p = 0; p < NP; p++) {
                ffma2(acc[m][p], xlo, wv[p].x);
                ffma2(acc[m][p], xhi, wv[p].y);
            }
        }

        mbar_arrive(smem_u32 + 64 + slot * 8);                            // empty
    }

    // Prompt tail
    {
        const int po = MODEL_DIM + 2 * lane;
        ulonglong2 wp[NP];
#pragma unroll
        for (int p = 0; p < NP; p++)
            wp[p] = *(const ulonglong2*)&wsp[p * DSTRIDE + po];
#pragma unroll
        for (int m = 0; m < T_TPW; m++) {
            const int t = tbase + w * T_TPW + m;
            const float2 pv = *(const float2*)(prompt + (size_t)t * PROMPT_DIM + 2 * lane);
            const unsigned long long plo = dup2(pv.x);
            const unsigned long long phi = dup2(pv.y);
#pragma unroll
            for (int p = 0; p < NP; p++) {
                ffma2(acc[m][p], plo, wp[p].x);
                ffma2(acc[m][p], phi, wp[p].y);
            }
        }
    }

    float accf[T_TPW][NE];
#pragma unroll
    for (int m = 0; m < T_TPW; m++)
#pragma unroll
        for (int p = 0; p < NP; p++)
            unpack2(acc[m][p], accf[m][2 * p], accf[m][2 * p + 1]);

#pragma unroll
    for (int off = 16; off > 0; off >>= 1) {
#pragma unroll
        for (int m = 0; m < T_TPW; m++)
#pragma unroll
            for (int e = 0; e < NE; e++)
                accf[m][e] += __shfl_xor_sync(0xffffffffu, accf[m][e], off);
    }

    if (lane < T_TPW) {
        const int t = tbase + w * T_TPW + lane;
        float lg[NE];
#pragma unroll
        for (int m = 0; m < T_TPW; m++) {
            if (lane == m) {
#pragma unroll
                for (int e = 0; e < NE; e++) lg[e] = accf[m][e];
            }
        }
        gate_epilogue(lg, b, t, out);
    }
}

// ================= Fallback kernel (R6, proven 33.1 us) =================
__global__ __launch_bounds__(F_THREADS, 1)
void topkgate_fb_kernel(const float* __restrict__ x,
                        const float* __restrict__ prompt,
                        const float* __restrict__ W,
                        const float* __restrict__ b,
                        float* __restrict__ out)
{
    extern __shared__ float2 wsp[];
    const int tid   = threadIdx.x;
    const int w     = tid >> 5;
    const int lane  = tid & 31;
    const int tbase = blockIdx.x * TPB + w * F_TPW;

    {
        const float2* Wv = (const float2*)W;
        for (int i = tid; i < KTOT * NP; i += F_THREADS) {
            int d = i >> 2;
            int p = i & 3;
            wsp[p * DSTRIDE + d] = Wv[i];
        }
    }
    __syncthreads();

    const float* xr0 = x + (size_t)(tbase + 0) * MODEL_DIM + 2 * lane;
    const float* xr1 = x + (size_t)(tbase + 1) * MODEL_DIM + 2 * lane;

    unsigned long long acc[F_TPW][NP];
#pragma unroll
    for (int m = 0; m < F_TPW; m++)
#pragma unroll
        for (int p = 0; p < NP; p++) acc[m][p] = 0ull;

    float2 buf[RING][F_TPW];
#pragma unroll
    for (int q = 0; q < RING - 1; q++) {
        buf[q][0] = __ldcs((const float2*)(xr0 + q * CHUNK));
        buf[q][1] = __ldcs((const float2*)(xr1 + q * CHUNK));
    }

    for (int it = 0; it < NIT; it += RING) {
#pragma unroll
        for (int u = 0; u < RING; u++) {
            const int j = it + u;
            if (j + (RING - 1) < NIT) {
                buf[(u + RING - 1) & (RING - 1)][0] =
                    __ldcs((const float2*)(xr0 + (j + RING - 1) * CHUNK));
                buf[(u + RING - 1) & (RING - 1)][1] =
                    __ldcs((const float2*)(xr1 + (j + RING - 1) * CHUNK));
            }
            const int d0 = j * CHUNK + 2 * lane;
            ulonglong2 wv[NP];
#pragma unroll
            for (int p = 0; p < NP; p++)
                wv[p] = *(const ulonglong2*)&wsp[p * DSTRIDE + d0];
#pragma unroll
            for (int m = 0; m < F_TPW; m++) {
                const float2 xv = buf[u][m];
                const unsigned long long xlo = dup2(xv.x);
                const unsigned long long xhi = dup2(xv.y);
#pragma unroll
                for (int p = 0; p < NP; p++) {
                    ffma2(acc[m][p], xlo, wv[p].x);
                    ffma2(acc[m][p], xhi, wv[p].y);
                }
            }
        }
    }

    {
        const int po = MODEL_DIM + 2 * lane;
        ulonglong2 wp[NP];
#pragma unroll
        for (int p = 0; p < NP; p++)
            wp[p] = *(const ulonglong2*)&wsp[p * DSTRIDE + po];
#pragma unroll
        for (int m = 0; m < F_TPW; m++) {
            const float2 pv = *(const float2*)(prompt + (size_t)(tbase + m) * PROMPT_DIM + 2 * lane);
            const unsigned long long plo = dup2(pv.x);
            const unsigned long long phi = dup2(pv.y);
#pragma unroll
            for (int p = 0; p < NP; p++) {
                ffma2(acc[m][p], plo, wp[p].x);
                ffma2(acc[m][p], phi, wp[p].y);
            }
        }
    }

    float accf[F_TPW][NE];
#pragma unroll
    for (int m = 0; m < F_TPW; m++)
#pragma unroll
        for (int p = 0; p < NP; p++)
            unpack2(acc[m][p], accf[m][2 * p], accf[m][2 * p + 1]);

#pragma unroll
    for (int off = 16; off > 0; off >>= 1) {
#pragma unroll
        for (int m = 0; m < F_TPW; m++)
#pragma unroll
            for (int e = 0; e < NE; e++)
                accf[m][e] += __shfl_xor_sync(0xffffffffu, accf[m][e], off);
    }

    if (lane < F_TPW) {
        const int t = tbase + lane;
        float lg[NE];
#pragma unroll
        for (int m = 0; m < F_TPW; m++) {
            if (lane == m) {
#pragma unroll
                for (int e = 0; e < NE; e++) lg[e] = accf[m][e];
            }
        }
        gate_epilogue(lg, b, t, out);
    }
}

// ================= Host =================
typedef CUresult (*EncodeTiledFn)(
    CUtensorMap*, CUtensorMapDataType, cuuint32_t, void*,
    const cuuint64_t*, const cuuint64_t*, const cuuint32_t*, const cuuint32_t*,
    CUtensorMapInterleave, CUtensorMapSwizzle, CUtensorMapL2promotion,
    CUtensorMapFloatOOBfill);

extern "C" void kernel_launch(void* const* d_in, const int* in_sizes, int n_in,
                              void* d_out, int out_size)
{
    const float* x      = (const float*)d_in[0];
    const float* prompt = (const float*)d_in[1];
    const float* W      = (const float*)d_in[2];
    const float* b      = (const float*)d_in[3];
    float* out          = (float*)d_out;

    // Try to build the TMA tensormap via the driver entry point (no -lcuda link).
    void* fn = nullptr;
    cudaDriverEntryPointQueryResult qres = cudaDriverEntryPointSymbolNotFound;
#if CUDART_VERSION >= 13000
    cudaGetDriverEntryPointByVersion("cuTensorMapEncodeTiled", &fn, 12000,
                                     cudaEnableDefault, &qres);
#else
    cudaGetDriverEntryPoint("cuTensorMapEncodeTiled", &fn, cudaEnableDefault, &qres);
#endif

    bool use_tma = false;
    CUtensorMap tmap;
    if (fn != nullptr && qres == cudaDriverEntryPointSuccess) {
        cuuint64_t dims[2]    = {MODEL_DIM, TOKENS};
        cuuint64_t strides[1] = {MODEL_DIM * sizeof(float)};
        cuuint32_t box[2]     = {CHUNK, TPB};
        cuuint32_t estr[2]    = {1, 1};
        memset(&tmap, 0, sizeof(tmap));
        CUresult r = ((EncodeTiledFn)fn)(
            &tmap, CU_TENSOR_MAP_DATA_TYPE_FLOAT32, 2, (void*)x,
            dims, strides, box, estr,
            CU_TENSOR_MAP_INTERLEAVE_NONE, CU_TENSOR_MAP_SWIZZLE_NONE,
            CU_TENSOR_MAP_L2_PROMOTION_L2_128B, CU_TENSOR_MAP_FLOAT_OOB_FILL_NONE);
        use_tma = (r == CUDA_SUCCESS);
    }

    if (use_tma) {
        cudaFuncSetAttribute(topkgate_tma_kernel,
                             cudaFuncAttributeMaxDynamicSharedMemorySize, T_SMEM);
        topkgate_tma_kernel<<<TOKENS / TPB, T_THREADS, T_SMEM>>>(tmap, prompt, W, b, out);
    } else {
        cudaFuncSetAttribute(topkgate_fb_kernel,
                             cudaFuncAttributeMaxDynamicSharedMemorySize, F_SMEM);
        topkgate_fb_kernel<<<TOKENS / TPB, F_THREADS, F_SMEM>>>(x, prompt, W, b, out);
    }
}

// round 11
// speedup vs baseline: 2.6746x; 1.2443x over previous
#include <cuda_runtime.h>
#include <math.h>

#define TOKENS     8192
#define MODEL_DIM  4096
#define PROMPT_DIM 64
#define KTOT       (MODEL_DIM + PROMPT_DIM)   // 4160
#define NE         8
#define NP         4                          // expert pairs
#define TPW        2                          // tokens per warp
#define WARPS      28
#define TPB        (TPW * WARPS)              // 56 tokens per block
#define THREADS    896
#define GRID       ((TOKENS + TPB - 1) / TPB) // 147 CTAs ~= full chip
#define DSTRIDE    4162                       // per-pair row, float2 units
#define SMEM_BYTES (NP * DSTRIDE * 8)         // 133,184 B
#define CHUNK      64                         // dims per K-chunk (float2 per lane)
#define NIT        (MODEL_DIM / CHUNK)        // 64
#define RING       4                          // prefetch distance 3

// d = a*b + d elementwise on packed fp32x2
__device__ __forceinline__ void ffma2(unsigned long long& d,
                                      unsigned long long a,
                                      unsigned long long b) {
    asm("fma.rn.f32x2 %0, %1, %2, %0;" : "+l"(d) : "l"(a), "l"(b));
}
__device__ __forceinline__ unsigned long long dup2(float v) {
    unsigned long long r;
    asm("mov.b64 %0, {%1, %1};" : "=l"(r) : "f"(v));
    return r;
}
__device__ __forceinline__ void unpack2(unsigned long long v, float& lo, float& hi) {
    asm("mov.b64 {%0, %1}, %2;" : "=f"(lo), "=f"(hi) : "l"(v));
}

__global__ __launch_bounds__(THREADS, 1)
void topkgate_kernel(const float* __restrict__ x,
                     const float* __restrict__ prompt,
                     const float* __restrict__ W,
                     const float* __restrict__ b,
                     float* __restrict__ out)
{
    extern __shared__ float2 wsp[];   // wsp[p * DSTRIDE + d] = (W[d][2p], W[d][2p+1])

    const int tid   = threadIdx.x;
    const int w     = tid >> 5;
    const int lane  = tid & 31;
    const int tbase = blockIdx.x * TPB + w * TPW;
    // Clamp for the tail CTA: reads duplicate the last rows, writes are guarded.
    const int tb    = (tbase > TOKENS - TPW) ? (TOKENS - TPW) : tbase;

    const float* xr0 = x + (size_t)(tb + 0) * MODEL_DIM + 2 * lane;
    const float* xr1 = x + (size_t)(tb + 1) * MODEL_DIM + 2 * lane;

    // ---- Issue ring-prologue x loads FIRST: their DRAM latency and the MSHR
    //      ramp overlap the W staging below. ----
    float2 buf[RING][TPW];
#pragma unroll
    for (int q = 0; q < RING - 1; q++) {
        buf[q][0] = __ldcs((const float2*)(xr0 + q * CHUNK));
        buf[q][1] = __ldcs((const float2*)(xr1 + q * CHUNK));
    }

    // ---- Stage W into expert-paired SMEM layout (overlaps with loads above) ----
    {
        const float2* Wv = (const float2*)W;   // Wv[d*4 + p] = (W[d][2p], W[d][2p+1])
        for (int i = tid; i < KTOT * NP; i += THREADS) {
            int d = i >> 2;
            int p = i & 3;
            wsp[p * DSTRIDE + d] = Wv[i];
        }
    }
    __syncthreads();

    // Packed accumulators: acc[m][p] = (logit[2p], logit[2p+1]) partial sums
    unsigned long long acc[TPW][NP];
#pragma unroll
    for (int m = 0; m < TPW; m++)
#pragma unroll
        for (int p = 0; p < NP; p++) acc[m][p] = 0ull;

    // ---- Mainloop: 4-deep register ring, prefetch distance 3 ----
    for (int it = 0; it < NIT; it += RING) {
#pragma unroll
        for (int u = 0; u < RING; u++) {
            const int j = it + u;

            // Prefetch chunk j+3 into ring slot (u+3)&3
            if (j + (RING - 1) < NIT) {
                buf[(u + RING - 1) & (RING - 1)][0] =
                    __ldcs((const float2*)(xr0 + (j + RING - 1) * CHUNK));
                buf[(u + RING - 1) & (RING - 1)][1] =
                    __ldcs((const float2*)(xr1 + (j + RING - 1) * CHUNK));
            }

            // W slice: dims (d0, d0+1) for all 4 expert pairs — LDS.128, conflict-free
            const int d0 = j * CHUNK + 2 * lane;
            ulonglong2 wv[NP];
#pragma unroll
            for (int p = 0; p < NP; p++)
                wv[p] = *(const ulonglong2*)&wsp[p * DSTRIDE + d0];
            // wv[p].x = (W[d0][2p], W[d0][2p+1]); wv[p].y = same for dim d0+1

#pragma unroll
            for (int m = 0; m < TPW; m++) {
                const float2 xv = buf[u][m];
                const unsigned long long xlo = dup2(xv.x);
                const unsigned long long xhi = dup2(xv.y);
#pragma unroll
                for (int p = 0; p < NP; p++) {
                    ffma2(acc[m][p], xlo, wv[p].x);
                    ffma2(acc[m][p], xhi, wv[p].y);
                }
            }
        }
    }

    // ---- Prompt tail: lane handles dims (4096+2*lane, +1) for both tokens ----
    {
        const int po = MODEL_DIM + 2 * lane;
        ulonglong2 wp[NP];
#pragma unroll
        for (int p = 0; p < NP; p++)
            wp[p] = *(const ulonglong2*)&wsp[p * DSTRIDE + po];
#pragma unroll
        for (int m = 0; m < TPW; m++) {
            const float2 pv = *(const float2*)(prompt + (size_t)(tb + m) * PROMPT_DIM + 2 * lane);
            const unsigned long long plo = dup2(pv.x);
            const unsigned long long phi = dup2(pv.y);
#pragma unroll
            for (int p = 0; p < NP; p++) {
                ffma2(acc[m][p], plo, wp[p].x);
                ffma2(acc[m][p], phi, wp[p].y);
            }
        }
    }

    // ---- Unpack to scalar accumulators ----
    float accf[TPW][NE];
#pragma unroll
    for (int m = 0; m < TPW; m++)
#pragma unroll
        for (int p = 0; p < NP; p++)
            unpack2(acc[m][p], accf[m][2 * p], accf[m][2 * p + 1]);

    // ---- Warp butterfly reduction over lanes ----
#pragma unroll
    for (int off = 16; off > 0; off >>= 1) {
#pragma unroll
        for (int m = 0; m < TPW; m++)
#pragma unroll
            for (int e = 0; e < NE; e++)
                accf[m][e] += __shfl_xor_sync(0xffffffffu, accf[m][e], off);
    }

    // ---- Epilogue: lane m handles token (tb + m); guard tail writes ----
    if (lane < TPW) {
        const int t = tb + lane;
        if (tbase + lane < TOKENS) {    // tail CTA: only true owners write
            float lg[NE];
#pragma unroll
            for (int m = 0; m < TPW; m++) {
                if (lane == m) {
#pragma unroll
                    for (int e = 0; e < NE; e++) lg[e] = accf[m][e];
                }
            }
#pragma unroll
            for (int e = 0; e < NE; e++) lg[e] += b[e];

            // Top-2 with first-index tie-break (matches jax.lax.top_k)
            int i0 = 0; float m0 = lg[0];
#pragma unroll
            for (int e = 1; e < NE; e++)
                if (lg[e] > m0) { m0 = lg[e]; i0 = e; }
            int i1 = -1; float m1 = -INFINITY;
#pragma unroll
            for (int e = 0; e < NE; e++)
                if (e != i0 && lg[e] > m1) { m1 = lg[e]; i1 = e; }

            // Softmax over 8, gather top-2, renormalize with EPS clamp
            float s = 0.0f;
#pragma unroll
            for (int e = 0; e < NE; e++) s += __expf(lg[e] - m0);
            const float g0 = 1.0f / s;
            const float g1 = __expf(m1 - m0) / s;
            const float denom = fmaxf(g0 + g1, 1.1920929e-07f);
            const float r0 = g0 / denom;
            const float r1 = g1 / denom;

            // masks: [T, 2, 8] at offset 0
            float* mrow = out + (size_t)t * 16;
            const float4 z = make_float4(0.f, 0.f, 0.f, 0.f);
            *(float4*)(mrow + 0)  = z;
            *(float4*)(mrow + 4)  = z;
            *(float4*)(mrow + 8)  = z;
            *(float4*)(mrow + 12) = z;
            mrow[i0]     = 1.0f;
            mrow[8 + i1] = 1.0f;

            // gates_s: [T, 2] at offset T*16
            float* grow = out + (size_t)TOKENS * 16 + (size_t)t * 2;
            grow[0] = r0;
            grow[1] = r1;
        }
    }
}

extern "C" void kernel_launch(void* const* d_in, const int* in_sizes, int n_in,
                              void* d_out, int out_size)
{
    const float* x      = (const float*)d_in[0];
    const float* prompt = (const float*)d_in[1];
    const float* W      = (const float*)d_in[2];
    const float* b      = (const float*)d_in[3];
    float* out          = (float*)d_out;

    cudaFuncSetAttribute(topkgate_kernel,
                         cudaFuncAttributeMaxDynamicSharedMemorySize, SMEM_BYTES);

    topkgate_kernel<<<GRID, THREADS, SMEM_BYTES>>>(x, prompt, W, b, out);
}